// round 16
// baseline (speedup 1.0000x reference)
#include <cuda_runtime.h>
#include <cuda_bf16.h>
#include <cstdint>

#define BB 64
#define TT 20
#define LL 196
#define HH 512
#define VV 30000

// ---------------- device scratch ----------------
__device__ float g_s[2 * BB * 1024];        // ping-pong [ctx | h], tf32
__device__ float g_hc[BB * 1024];           // [h | c], tf32
__device__ float g_c[BB * HH];              // cell state, EXACT fp32 (block-private)
__device__ float g_q[BB * HH];              // query, fp32
__device__ float g_emb[BB * TT * HH];       // tf32
__device__ float g_embpart[BB * TT * 2048]; // fp32 (GEMM out, bias included)
__device__ float g_keyproj[BB * LL * HH];   // fp32
__device__ float g_ctxall[BB * TT * HH];    // tf32
__device__ float g_Wcomb[1024 * 2048];      // tf32, K-major, gate-interleaved
__device__ float g_Wq2[1024 * HH];          // tf32
__device__ float g_WembT[HH * 2048];        // tf32, gate-interleaved
__device__ float g_blstm2[2048];            // fp32 bias, gate-interleaved
__device__ volatile unsigned g_bar[64];     // device-wide barrier counters

// ---------------- helpers ----------------
__device__ __forceinline__ float to_tf32(float x) {
    float r; asm("cvt.rna.tf32.f32 %0, %1;" : "=f"(r) : "f"(x)); return r;
}
__device__ __forceinline__ float sigmoidf_(float x) {
    return __fdividef(1.f, 1.f + __expf(-x));
}
__device__ __forceinline__ float tanh_acc(float x) {
    x = fminf(fmaxf(x, -15.f), 15.f);
    float e = __expf(2.f * x);
    return __fdividef(e - 1.f, e + 1.f);
}
__device__ __forceinline__ float tanha(float x) {
    float r; asm("tanh.approx.f32 %0, %1;" : "=f"(r) : "f"(x)); return r;
}
__device__ __forceinline__ void cpa16(float* dst, const float* src) {
    uint32_t d = (uint32_t)__cvta_generic_to_shared(dst);
    asm volatile("cp.async.cg.shared.global [%0], [%1], 16;\n" :: "r"(d), "l"(src));
}
__device__ __forceinline__ void cpa16g(float* dst, const float* src, bool p) {
    uint32_t d = (uint32_t)__cvta_generic_to_shared(dst);
    int b = p ? 16 : 0;
    asm volatile("cp.async.cg.shared.global [%0], [%1], 16, %2;\n" :: "r"(d), "l"(src), "r"(b));
}
#define CP_COMMIT() asm volatile("cp.async.commit_group;\n")
#define CP_WAIT(n)  asm volatile("cp.async.wait_group %0;\n" :: "n"(n))

// device-wide barrier (all 64 blocks arrive; counters zeroed per launch)
__device__ __forceinline__ void gbar(int idx) {
    __syncthreads();
    if (threadIdx.x == 0) {
        __threadfence();
        atomicAdd((unsigned*)&g_bar[idx], 1u);
        while (g_bar[idx] < 64u) { }
    }
    __syncthreads();
}

__global__ void k_zero_bar() {
    if (threadIdx.x < 64) *((unsigned*)&g_bar[threadIdx.x]) = 0u;
}

// ---------------- prep: coalesced transposes + tf32 ----------------
__global__ void k_prep_w(const float* __restrict__ W_ih, const float* __restrict__ W_hh) {
    __shared__ float tile[32][33];
    int tx = threadIdx.x, ty = threadIdx.y;
    int jp0 = blockIdx.x * 32;
    int yy = blockIdx.y;
    if (yy < 32) {
        int k0 = yy * 32;
        int jp = jp0 + ty;
        int u = jp >> 2, g = jp & 3;
        int j = g * 512 + u;
        int k = k0 + tx;
        tile[ty][tx] = (k < 512) ? W_ih[j * 1024 + 512 + k] : W_hh[j * 512 + (k - 512)];
        __syncthreads();
        g_Wcomb[(size_t)(k0 + ty) * 2048 + jp0 + tx] = to_tf32(tile[tx][ty]);
    } else {
        int k0 = (yy - 32) * 32;
        int jp = jp0 + ty;
        int u = jp >> 2, g = jp & 3;
        int j = g * 512 + u;
        tile[ty][tx] = W_ih[j * 1024 + k0 + tx];
        __syncthreads();
        g_WembT[(size_t)(k0 + ty) * 2048 + jp0 + tx] = to_tf32(tile[tx][ty]);
    }
}

__global__ void k_prep_misc(const float* __restrict__ Wq, const float* __restrict__ Wm,
                            const float* __restrict__ Wc, const float* __restrict__ b_lstm) {
    int i = blockIdx.x * blockDim.x + threadIdx.x;
    if (i < 1024 * 512) {
        int k = i >> 9, a = i & 511;
        float v = (k < 512) ? (Wq[i] + Wm[i]) : Wc[(k - 512) * 512 + a];
        g_Wq2[i] = to_tf32(v);
    }
    if (i < 2048) {
        int u = i >> 2, g = i & 3;
        g_blstm2[i] = b_lstm[g * 512 + u];
    }
    if (i < BB * 512) {   // ctx0 = 0 in ping buffer 0
        int b = i >> 9, d = i & 511;
        g_s[b * 1024 + d] = 0.f;
    }
}

__global__ void k_gather(const int* __restrict__ cap, const float* __restrict__ emb_tab) {
    int i = blockIdx.x * blockDim.x + threadIdx.x;
    if (i < BB * TT * HH) {
        int bt = i >> 9, e = i & 511;
        g_emb[i] = to_tf32(emb_tab[(size_t)cap[bt] * HH + e]);
    }
}

// ---------------- cp.async 3-stage tf32 GEMM (256 thr): C = A@B (+bias) ----------------
template <int BM, int BN, bool CVT_OUT, bool CVT_A, bool CVT_B>
__global__ __launch_bounds__(256)
void k_gemmf(const float* __restrict__ A, int lda,
             const float* __restrict__ Bm, int ldb,
             float* __restrict__ C, int ldc,
             const float* __restrict__ bias,
             int M, int N, int K) {
    constexpr int BK = 32;
    constexpr int ASf = BM * 36;
    constexpr int BSf = BK * (BN + 8);
    constexpr int STG = ASf + BSf;
    constexpr int WTM = BM / 2, WTN = BN / 4;
    constexpr int MI = WTM / 16, NI = WTN / 8;
    constexpr int AC = BM * 8 / 256;
    constexpr int BC = (BN / 4) * 32 / 256;

    extern __shared__ float sm[];
    const int tid = threadIdx.x;
    const int warp = tid >> 5, lane = tid & 31;
    const int wm = warp & 1, wn = warp >> 1;
    const int grp = lane >> 2, tig = lane & 3;
    const int m0 = blockIdx.y * BM;
    const int n0 = blockIdx.x * BN;
    const int KT = K / BK;

    float acc[MI][NI][4];
#pragma unroll
    for (int i = 0; i < MI; i++)
#pragma unroll
        for (int j = 0; j < NI; j++)
#pragma unroll
            for (int r = 0; r < 4; r++) acc[i][j][r] = 0.f;

    auto issue = [&](int st, int kt) {
        float* base = sm + st * STG;
#pragma unroll
        for (int i = 0; i < AC; i++) {
            int c = tid + i * 256;
            int row = c >> 3, kc = (c & 7) << 2;
            cpa16(base + row * 36 + kc, A + (size_t)(m0 + row) * lda + kt * BK + kc);
        }
#pragma unroll
        for (int i = 0; i < BC; i++) {
            int c = tid + i * 256;
            int kr = c / (BN / 4), nc = (c % (BN / 4)) << 2;
            int gn = n0 + nc;
            bool ok = gn < N;
            cpa16g(base + ASf + kr * (BN + 8) + nc,
                   Bm + (size_t)(kt * BK + kr) * ldb + (ok ? gn : 0), ok);
        }
        CP_COMMIT();
    };

    issue(0, 0);
    issue(1, 1);

#pragma unroll 1
    for (int kt = 0; kt < KT; kt++) {
        int st = kt % 3;
        if (kt < KT - 1) { CP_WAIT(1); } else { CP_WAIT(0); }
        __syncthreads();
        if (kt + 2 < KT) issue((kt + 2) % 3, kt + 2);

        const float* As = sm + st * STG;
        const float* Bs = As + ASf;
#pragma unroll
        for (int kk = 0; kk < BK; kk += 8) {
            uint32_t af[MI][4], bf[NI][2];
#pragma unroll
            for (int mi = 0; mi < MI; mi++) {
                int rb = wm * WTM + mi * 16;
                float a0 = As[(rb + grp) * 36 + kk + tig];
                float a1 = As[(rb + grp + 8) * 36 + kk + tig];
                float a2 = As[(rb + grp) * 36 + kk + tig + 4];
                float a3 = As[(rb + grp + 8) * 36 + kk + tig + 4];
                if (CVT_A) { a0 = to_tf32(a0); a1 = to_tf32(a1); a2 = to_tf32(a2); a3 = to_tf32(a3); }
                af[mi][0] = __float_as_uint(a0); af[mi][1] = __float_as_uint(a1);
                af[mi][2] = __float_as_uint(a2); af[mi][3] = __float_as_uint(a3);
            }
#pragma unroll
            for (int ni = 0; ni < NI; ni++) {
                int cb = wn * WTN + ni * 8 + grp;
                float b0 = Bs[(kk + tig) * (BN + 8) + cb];
                float b1 = Bs[(kk + tig + 4) * (BN + 8) + cb];
                if (CVT_B) { b0 = to_tf32(b0); b1 = to_tf32(b1); }
                bf[ni][0] = __float_as_uint(b0); bf[ni][1] = __float_as_uint(b1);
            }
#pragma unroll
            for (int mi = 0; mi < MI; mi++)
#pragma unroll
                for (int ni = 0; ni < NI; ni++) {
                    asm volatile(
                        "mma.sync.aligned.m16n8k8.row.col.f32.tf32.tf32.f32 "
                        "{%0,%1,%2,%3}, {%4,%5,%6,%7}, {%8,%9}, {%0,%1,%2,%3};\n"
                        : "+f"(acc[mi][ni][0]), "+f"(acc[mi][ni][1]),
                          "+f"(acc[mi][ni][2]), "+f"(acc[mi][ni][3])
                        : "r"(af[mi][0]), "r"(af[mi][1]), "r"(af[mi][2]), "r"(af[mi][3]),
                          "r"(bf[ni][0]), "r"(bf[ni][1]));
                }
        }
    }

#pragma unroll
    for (int mi = 0; mi < MI; mi++) {
#pragma unroll
        for (int ni = 0; ni < NI; ni++) {
            int row0 = m0 + wm * WTM + mi * 16 + grp;
            int col0 = n0 + wn * WTN + ni * 8 + tig * 2;
            if (col0 < N) {
                float b0 = bias ? bias[col0] : 0.f;
                float b1 = bias ? bias[col0 + 1] : 0.f;
                float v00 = acc[mi][ni][0] + b0, v01 = acc[mi][ni][1] + b1;
                float v10 = acc[mi][ni][2] + b0, v11 = acc[mi][ni][3] + b1;
                if (CVT_OUT) {
                    v00 = to_tf32(v00); v01 = to_tf32(v01);
                    v10 = to_tf32(v10); v11 = to_tf32(v11);
                }
                *reinterpret_cast<float2*>(C + (size_t)row0 * ldc + col0) = make_float2(v00, v01);
                *reinterpret_cast<float2*>(C + (size_t)(row0 + 8) * ldc + col0) = make_float2(v10, v11);
            }
        }
    }
}

// ---------------- 512-thread BM=128 x BN=256 GEMM (logits) ----------------
template <bool CVT_B>
__global__ __launch_bounds__(512)
void k_gemm512(const float* __restrict__ A, int lda,
               const float* __restrict__ Bm, int ldb,
               float* __restrict__ C, int ldc,
               const float* __restrict__ bias,
               int M, int N, int K) {
    constexpr int BM = 128, BN = 256, BK = 32;
    constexpr int ASf = BM * 36;
    constexpr int BSf = BK * (BN + 8);
    constexpr int STG = ASf + BSf;
    constexpr int WTM = 64, WTN = 32, MI = 4, NI = 4;

    extern __shared__ float sm[];
    const int tid = threadIdx.x;
    const int warp = tid >> 5, lane = tid & 31;
    const int wm = warp & 1, wn = warp >> 1;
    const int grp = lane >> 2, tig = lane & 3;
    const int m0 = blockIdx.y * BM;
    const int n0 = blockIdx.x * BN;
    const int KT = K / BK;

    float acc[MI][NI][4];
#pragma unroll
    for (int i = 0; i < MI; i++)
#pragma unroll
        for (int j = 0; j < NI; j++)
#pragma unroll
            for (int r = 0; r < 4; r++) acc[i][j][r] = 0.f;

    auto issue = [&](int st, int kt) {
        float* base = sm + st * STG;
#pragma unroll
        for (int i = 0; i < 2; i++) {
            int c = tid + i * 512;
            int row = c >> 3, kc = (c & 7) << 2;
            cpa16(base + row * 36 + kc, A + (size_t)(m0 + row) * lda + kt * BK + kc);
        }
#pragma unroll
        for (int i = 0; i < 4; i++) {
            int c = tid + i * 512;
            int kr = c >> 6, nc = (c & 63) << 2;
            int gn = n0 + nc;
            bool ok = gn < N;
            cpa16g(base + ASf + kr * (BN + 8) + nc,
                   Bm + (size_t)(kt * BK + kr) * ldb + (ok ? gn : 0), ok);
        }
        CP_COMMIT();
    };

    issue(0, 0);
    issue(1, 1);

#pragma unroll 1
    for (int kt = 0; kt < KT; kt++) {
        int st = kt % 3;
        if (kt < KT - 1) { CP_WAIT(1); } else { CP_WAIT(0); }
        __syncthreads();
        if (kt + 2 < KT) issue((kt + 2) % 3, kt + 2);

        const float* As = sm + st * STG;
        const float* Bs = As + ASf;
#pragma unroll
        for (int kk = 0; kk < BK; kk += 8) {
            uint32_t af[MI][4], bf[NI][2];
#pragma unroll
            for (int mi = 0; mi < MI; mi++) {
                int rb = wm * WTM + mi * 16;
                af[mi][0] = __float_as_uint(As[(rb + grp) * 36 + kk + tig]);
                af[mi][1] = __float_as_uint(As[(rb + grp + 8) * 36 + kk + tig]);
                af[mi][2] = __float_as_uint(As[(rb + grp) * 36 + kk + tig + 4]);
                af[mi][3] = __float_as_uint(As[(rb + grp + 8) * 36 + kk + tig + 4]);
            }
#pragma unroll
            for (int ni = 0; ni < NI; ni++) {
                int cb = wn * WTN + ni * 8 + grp;
                float b0 = Bs[(kk + tig) * (BN + 8) + cb];
                float b1 = Bs[(kk + tig + 4) * (BN + 8) + cb];
                if (CVT_B) { b0 = to_tf32(b0); b1 = to_tf32(b1); }
                bf[ni][0] = __float_as_uint(b0); bf[ni][1] = __float_as_uint(b1);
            }
#pragma unroll
            for (int mi = 0; mi < MI; mi++)
#pragma unroll
                for (int ni = 0; ni < NI; ni++) {
                    asm volatile(
                        "mma.sync.aligned.m16n8k8.row.col.f32.tf32.tf32.f32 "
                        "{%0,%1,%2,%3}, {%4,%5,%6,%7}, {%8,%9}, {%0,%1,%2,%3};\n"
                        : "+f"(acc[mi][ni][0]), "+f"(acc[mi][ni][1]),
                          "+f"(acc[mi][ni][2]), "+f"(acc[mi][ni][3])
                        : "r"(af[mi][0]), "r"(af[mi][1]), "r"(af[mi][2]), "r"(af[mi][3]),
                          "r"(bf[ni][0]), "r"(bf[ni][1]));
                }
        }
    }

#pragma unroll
    for (int mi = 0; mi < MI; mi++) {
#pragma unroll
        for (int ni = 0; ni < NI; ni++) {
            int row0 = m0 + wm * WTM + mi * 16 + grp;
            int col0 = n0 + wn * WTN + ni * 8 + tig * 2;
            if (col0 < N) {
                float b0 = bias ? bias[col0] : 0.f;
                float b1 = bias ? bias[col0 + 1] : 0.f;
                *reinterpret_cast<float2*>(C + (size_t)row0 * ldc + col0) =
                    make_float2(acc[mi][ni][0] + b0, acc[mi][ni][1] + b1);
                *reinterpret_cast<float2*>(C + (size_t)(row0 + 8) * ldc + col0) =
                    make_float2(acc[mi][ni][2] + b0, acc[mi][ni][3] + b1);
            }
        }
    }
}

// ---------------- persistent recurrence kernel ----------------
// 64x32 tile MMA (K=1024, BK=64, KT=16), 3-stage cp.async. acc[2][4].
__device__ __forceinline__ void mma_64x32(const float* __restrict__ A, int lda,
                                          const float* __restrict__ B, int ldb,
                                          float* sm, float (&acc)[2][4]) {
    constexpr int BK = 64, KT = 16;
    constexpr int ASf = 64 * 68;   // 4352
    constexpr int BSf = 64 * 40;   // 2560
    constexpr int STG = ASf + BSf; // 6912
    const int tid = threadIdx.x;
    const int warp = tid >> 5, lane = tid & 31;
    const int wm = warp & 1, wn = warp >> 1;
    const int grp = lane >> 2, tig = lane & 3;

#pragma unroll
    for (int mi = 0; mi < 2; mi++)
#pragma unroll
        for (int r = 0; r < 4; r++) acc[mi][r] = 0.f;

    auto issue = [&](int st, int kt) {
        float* base = sm + st * STG;
#pragma unroll
        for (int i = 0; i < 4; i++) {
            int c = tid + i * 256;
            int row = c >> 4, kc = (c & 15) << 2;
            cpa16(base + row * 68 + kc, A + (size_t)row * lda + kt * BK + kc);
        }
#pragma unroll
        for (int i = 0; i < 2; i++) {
            int c = tid + i * 256;
            int kr = c >> 3, nc = (c & 7) << 2;
            cpa16(base + ASf + kr * 40 + nc, B + (size_t)(kt * BK + kr) * ldb + nc);
        }
        CP_COMMIT();
    };

    issue(0, 0);
    issue(1, 1);

#pragma unroll 1
    for (int kt = 0; kt < KT; kt++) {
        int st = kt % 3;
        if (kt < KT - 1) { CP_WAIT(1); } else { CP_WAIT(0); }
        __syncthreads();
        if (kt + 2 < KT) issue((kt + 2) % 3, kt + 2);

        const float* As = sm + st * STG;
        const float* Bs = As + ASf;
#pragma unroll
        for (int kk = 0; kk < BK; kk += 8) {
            uint32_t af[2][4], bf[2];
#pragma unroll
            for (int mi = 0; mi < 2; mi++) {
                int rb = wm * 32 + mi * 16;
                af[mi][0] = __float_as_uint(As[(rb + grp) * 68 + kk + tig]);
                af[mi][1] = __float_as_uint(As[(rb + grp + 8) * 68 + kk + tig]);
                af[mi][2] = __float_as_uint(As[(rb + grp) * 68 + kk + tig + 4]);
                af[mi][3] = __float_as_uint(As[(rb + grp + 8) * 68 + kk + tig + 4]);
            }
            int cb = wn * 8 + grp;
            bf[0] = __float_as_uint(Bs[(kk + tig) * 40 + cb]);
            bf[1] = __float_as_uint(Bs[(kk + tig + 4) * 40 + cb]);
#pragma unroll
            for (int mi = 0; mi < 2; mi++) {
                asm volatile(
                    "mma.sync.aligned.m16n8k8.row.col.f32.tf32.tf32.f32 "
                    "{%0,%1,%2,%3}, {%4,%5,%6,%7}, {%8,%9}, {%0,%1,%2,%3};\n"
                    : "+f"(acc[mi][0]), "+f"(acc[mi][1]),
                      "+f"(acc[mi][2]), "+f"(acc[mi][3])
                    : "r"(af[mi][0]), "r"(af[mi][1]), "r"(af[mi][2]), "r"(af[mi][3]),
                      "r"(bf[0]), "r"(bf[1]));
            }
        }
    }
    __syncthreads();   // safe smem reuse after mainloop
}

__global__ __launch_bounds__(256, 1)
void k_persist(const float* __restrict__ feat, const float* __restrict__ v_att) {
    extern __shared__ float sm[];
    const int bid = blockIdx.x;       // 0..63
    const int tid = threadIdx.x;
    const int warp = tid >> 5, lane = tid & 31;
    const int wm = warp & 1, wn = warp >> 1;
    const int grp = lane >> 2, tig = lane & 3;

    for (int t = 0; t < TT; t++) {
        float* s_cur = g_s + (t & 1) * (BB * 1024);
        float* s_nxt = g_s + ((t + 1) & 1) * (BB * 1024);

        // ===== phase 1: gates GEMM (64x32 tile) + LSTM cell =====
        {
            const int n0 = bid * 32;
            float acc[2][4];
            mma_64x32(s_cur, 1024, g_Wcomb + n0, 2048, sm, acc);

            // stage gates (+embpart incl. bias) into smem
            float* gb = sm;   // [64][36]
#pragma unroll
            for (int mi = 0; mi < 2; mi++) {
                int row0 = wm * 32 + mi * 16 + grp;
                int col0 = wn * 8 + tig * 2;
#pragma unroll
                for (int r = 0; r < 4; r++) {
                    int row = row0 + ((r >= 2) ? 8 : 0);
                    int col = col0 + (r & 1);
                    gb[row * 36 + col] = acc[mi][r] +
                        g_embpart[(size_t)(row * TT + t) * 2048 + n0 + col];
                }
            }
            __syncthreads();

            const int U0 = bid * 8;
#pragma unroll
            for (int idx = tid; idx < 512; idx += 256) {
                int b = idx >> 3, ul = idx & 7;
                float4 g4 = *reinterpret_cast<float4*>(&gb[b * 36 + ul * 4]);
                float gi = sigmoidf_(g4.x);
                float gf = sigmoidf_(g4.y);
                float gg = tanh_acc(g4.z);
                float go = sigmoidf_(g4.w);
                int U = U0 + ul;
                float cn = gf * g_c[b * HH + U] + gi * gg;
                float h = go * tanh_acc(cn);
                g_c[b * HH + U] = cn;                 // block-private across steps
                float ht = to_tf32(h), ct = to_tf32(cn);
                s_nxt[b * 1024 + 512 + U] = ht;
                g_hc[b * 1024 + U] = ht;
                g_hc[b * 1024 + 512 + U] = ct;
            }
        }
        gbar(t * 3 + 0);

        // ===== phase 2: q GEMM (blocks 0..15, 64x32 tiles over N=512) =====
        if (bid < 16) {
            const int n0q = bid * 32;
            float acc[2][4];
            mma_64x32(g_hc, 1024, g_Wq2 + n0q, 512, sm, acc);
#pragma unroll
            for (int mi = 0; mi < 2; mi++) {
                int row0 = wm * 32 + mi * 16 + grp;
                int col0 = n0q + wn * 8 + tig * 2;
#pragma unroll
                for (int r = 0; r < 4; r++) {
                    int row = row0 + ((r >= 2) ? 8 : 0);
                    int col = col0 + (r & 1);
                    g_q[row * HH + col] = acc[mi][r];
                }
            }
        }
        gbar(t * 3 + 1);

        // ===== phase 3: attention (1 batch per block) =====
        {
            const int b = bid;
            float* qs = sm;             // 512
            float* vs = sm + 512;       // 512
            float* sc = sm + 1024;      // 200
            float* red = sm + 1224;     // 8

            for (int i = tid; i < HH; i += 256) {
                qs[i] = __ldcg(&g_q[b * HH + i]);
                vs[i] = v_att[i];
            }
            __syncthreads();

            for (int l = warp; l < LL; l += 8) {
                const float* kpl = g_keyproj + ((size_t)b * LL + l) * HH;
                float a = 0.f;
#pragma unroll 4
                for (int i = lane; i < HH; i += 32)
                    a += vs[i] * tanha(kpl[i] + qs[i]);
#pragma unroll
                for (int off = 16; off; off >>= 1) a += __shfl_xor_sync(0xffffffffu, a, off);
                if (!lane) sc[l] = a;
            }
            __syncthreads();

            float v = (tid < LL) ? sc[tid] : -1e30f;
            float mx = v;
#pragma unroll
            for (int off = 16; off; off >>= 1) mx = fmaxf(mx, __shfl_xor_sync(0xffffffffu, mx, off));
            if (!lane) red[warp] = mx;
            __syncthreads();
            if (tid == 0) {
                float m = red[0];
                for (int w = 1; w < 8; w++) m = fmaxf(m, red[w]);
                red[0] = m;
            }
            __syncthreads();
            mx = red[0];
            __syncthreads();
            float e = (tid < LL) ? __expf(v - mx) : 0.f;
            float sum = e;
#pragma unroll
            for (int off = 16; off; off >>= 1) sum += __shfl_xor_sync(0xffffffffu, sum, off);
            if (!lane) red[warp] = sum;
            __syncthreads();
            if (tid == 0) {
                float s2 = 0.f;
                for (int w = 0; w < 8; w++) s2 += red[w];
                red[0] = s2;
            }
            __syncthreads();
            float inv = __fdividef(1.f, red[0]);
            if (tid < LL) sc[tid] = e * inv;
            __syncthreads();

            for (int d = tid; d < HH; d += 256) {
                float a = 0.f;
                const float* fb = feat + (size_t)b * LL * HH + d;
#pragma unroll 4
                for (int l = 0; l < LL; l++) a += sc[l] * fb[(size_t)l * HH];
                float at = to_tf32(a);
                s_nxt[b * 1024 + d] = at;
                g_ctxall[((size_t)b * TT + t) * HH + d] = at;
            }
            __syncthreads();   // smem reuse next iteration
        }
        gbar(t * 3 + 2);
    }
}

// ---------------- host launcher ----------------
extern "C" void kernel_launch(void* const* d_in, const int* in_sizes, int n_in,
                              void* d_out, int out_size) {
    const int*   captions  = (const int*)d_in[0];
    const float* feat      = (const float*)d_in[1];
    const float* pooled    = (const float*)d_in[2];
    const float* embedding = (const float*)d_in[4];
    const float* W_ih      = (const float*)d_in[5];
    const float* W_hh      = (const float*)d_in[6];
    const float* b_lstm    = (const float*)d_in[7];
    const float* Wq        = (const float*)d_in[8];
    const float* Wk        = (const float*)d_in[9];
    const float* Wm        = (const float*)d_in[10];
    const float* Wc        = (const float*)d_in[11];
    const float* v_att     = (const float*)d_in[12];
    const float* W_out     = (const float*)d_in[13];
    const float* b_out     = (const float*)d_in[14];
    const float* W_init_h  = (const float*)d_in[15];
    const float* b_init_h  = (const float*)d_in[16];
    const float* W_init_c  = (const float*)d_in[17];
    const float* b_init_c  = (const float*)d_in[18];
    float* out = (float*)d_out;

    float *p_s, *p_emb, *p_embpart, *p_keyproj, *p_ctxall;
    float *p_WembT, *p_blstm2, *p_c;
    cudaGetSymbolAddress((void**)&p_s, g_s);
    cudaGetSymbolAddress((void**)&p_emb, g_emb);
    cudaGetSymbolAddress((void**)&p_embpart, g_embpart);
    cudaGetSymbolAddress((void**)&p_keyproj, g_keyproj);
    cudaGetSymbolAddress((void**)&p_ctxall, g_ctxall);
    cudaGetSymbolAddress((void**)&p_WembT, g_WembT);
    cudaGetSymbolAddress((void**)&p_blstm2, g_blstm2);
    cudaGetSymbolAddress((void**)&p_c, g_c);

    constexpr int SM_BIG  = 3 * (128 * 36 + 32 * 136) * 4;   // 107520
    constexpr int SM_MED  = 3 * (64 * 36 + 32 * 136) * 4;    // 79872
    constexpr int SM_512  = 3 * (128 * 36 + 32 * 264) * 4;   // 156672
    constexpr int SM_PERS = 3 * (64 * 68 + 64 * 40) * 4;     // 82944
    cudaFuncSetAttribute((const void*)k_gemmf<128, 128, false, false, false>,
                         cudaFuncAttributeMaxDynamicSharedMemorySize, SM_BIG);
    cudaFuncSetAttribute((const void*)k_gemmf<128, 128, false, true, true>,
                         cudaFuncAttributeMaxDynamicSharedMemorySize, SM_BIG);
    cudaFuncSetAttribute((const void*)k_gemmf<64, 128, true, true, true>,
                         cudaFuncAttributeMaxDynamicSharedMemorySize, SM_MED);
    cudaFuncSetAttribute((const void*)k_gemmf<64, 128, false, true, true>,
                         cudaFuncAttributeMaxDynamicSharedMemorySize, SM_MED);
    cudaFuncSetAttribute((const void*)k_gemm512<true>,
                         cudaFuncAttributeMaxDynamicSharedMemorySize, SM_512);
    cudaFuncSetAttribute((const void*)k_persist,
                         cudaFuncAttributeMaxDynamicSharedMemorySize, SM_PERS);

    // ---- prologue ----
    k_zero_bar<<<1, 64>>>();
    k_prep_w<<<dim3(64, 48), dim3(32, 32)>>>(W_ih, W_hh);
    k_prep_misc<<<2048, 256>>>(Wq, Wm, Wc, b_lstm);
    k_gather<<<(BB * TT * HH + 255) / 256, 256>>>(captions, embedding);

    // h0 / c0 via tensor cores (cvt in-kernel)
    k_gemmf<64, 128, true, true, true><<<dim3(4, 1), 256, SM_MED>>>(
        pooled, 512, W_init_h, 512, p_s + 512, 1024, b_init_h, BB, 512, 512);
    k_gemmf<64, 128, false, true, true><<<dim3(4, 1), 256, SM_MED>>>(
        pooled, 512, W_init_c, 512, p_c, 512, b_init_c, BB, 512, 512);

    // emb_part = emb @ WembT + b   (M=1280, N=2048, K=512)
    k_gemmf<128, 128, false, false, false><<<dim3(16, 10), 256, SM_BIG>>>(
        p_emb, 512, p_WembT, 2048, p_embpart, 2048, p_blstm2, BB * TT, 2048, 512);
    // key_proj = feat @ Wk (both cvt in-kernel)  (M=12544, N=512, K=512)
    k_gemmf<128, 128, false, true, true><<<dim3(4, 98), 256, SM_BIG>>>(
        feat, 512, Wk, 512, p_keyproj, 512, nullptr, BB * LL, 512, 512);

    // ---- entire recurrence in ONE persistent kernel ----
    k_persist<<<64, 256, SM_PERS>>>(feat, v_att);

    // ---- logits = ctx_all @ W_out(cvt in-kernel) + b_out ----
    k_gemm512<true><<<dim3((VV + 255) / 256, 10), 512, SM_512>>>(
        p_ctxall, 512, W_out, VV, out, VV, b_out, BB * TT, VV, 512);
}